// round 6
// baseline (speedup 1.0000x reference)
#include <cuda_runtime.h>

// Problem constants
static constexpr int LD  = 4;       // LOCAL_DIM
static constexpr int MD  = 64;      // M
static constexpr int TRI = 89440;   // sum_{k=1..64} k^2  (reachable (l,u,dn) tuples)

// epsilon strides (elements): shape (4, 64, 64, 65, 65) = (d, m, l, u, dn)
static constexpr unsigned long long SD = 17305600ull; // 64*64*65*65
static constexpr unsigned long long SM = 270400ull;   // 64*65*65
static constexpr unsigned long long SL = 4225ull;     // 65*65

static constexpr int NGROUP = 64;   // batch groups for the mark pass
static constexpr int NW     = 2080; // mask words per d: sum_{l} (l+1) = 65*64/2

// Scratch: transposed reachable region, layout [d][loff(l)+u*(l+1)+dn][m]
__device__ float g_scratch[(size_t)LD * TRI * MD];
// Per-group realized-tuple mask slices (plain stores, OR-reduced by transpose)
__device__ unsigned long long g_slice[NGROUP][LD][NW];

__device__ __host__ __forceinline__ int loff(int l) {
    return l * (l + 1) * (2 * l + 1) / 6;   // sum_{k=1..l} k^2
}

// Per-warp dtype detection: words 1,3,..,63 of the indices buffer are all zero
// iff the buffer is int64 (values < 4). Always in-bounds under either dtype.
__device__ __forceinline__ bool detect_is64(const void* raw, int lane) {
    unsigned wodd = ((const unsigned*)raw)[2 * lane + 1];
    return __ballot_sync(0xffffffffu, wodd != 0u) == 0u;
}

__device__ __forceinline__ int load_idx(const void* raw, size_t pos, bool is64) {
    if (is64) return (int)((const long long*)raw)[pos];
    return ((const int*)raw)[pos];
}

// ---------------------------------------------------------------------------
// Kernel 1: mark realized (d,l,u,dn) tuples — contention-free version.
// Grid (64 groups, 2 d-halves); block (64,4). Each block scans 128 batches,
// aggregates masks for its 2 assigned d values in SHARED memory (spread smem
// atomics only), then plain-stores its slice. No global atomics at all.
// ---------------------------------------------------------------------------
__global__ void __launch_bounds__(256) mark_tuples(const void* __restrict__ raw) {
    const int x     = threadIdx.x;         // site 0..63
    const int ty    = threadIdx.y;         // 0..3 batch-in-pass
    const int group = blockIdx.x;          // 0..63
    const int dh    = blockIdx.y;          // 0..1: handles d = 2*dh, 2*dh+1
    const int t     = ty * 64 + x;         // 0..255

    __shared__ unsigned long long sm[2][NW];   // 33.3 KB
    __shared__ unsigned s0[4][2], s1[4][2];

    for (int w = t; w < 2 * NW; w += 256)
        (&sm[0][0])[w] = 0ull;
    const bool is64 = detect_is64(raw, x & 31);
    __syncthreads();

    const int site_off = x * (x + 1) / 2;
    const int half = x >> 5;
    const unsigned lm = (1u << (x & 31)) - 1u;

    for (int p = 0; p < 32; ++p) {
        const int b = group * 128 + p * 4 + ty;
        const int idx = load_idx(raw, (size_t)b * 64 + x, is64);

        const unsigned m0 = __ballot_sync(0xffffffffu, idx & 1);
        const unsigned m1 = __ballot_sync(0xffffffffu, idx & 2);
        if ((x & 31) == 0) { s0[ty][half] = m0; s1[ty][half] = m1; }
        __syncthreads();
        const int u  = __popc(m0 & lm) + (half ? __popc(s0[ty][0]) : 0);
        const int dn = __popc(m1 & lm) + (half ? __popc(s1[ty][0]) : 0);

        if ((idx >> 1) == dh)
            atomicOr(&sm[idx & 1][site_off + u], 1ull << dn);
        __syncthreads();
    }

    for (int w = t; w < NW; w += 256) {
        g_slice[group][2 * dh + 0][w] = sm[0][w];
        g_slice[group][2 * dh + 1][w] = sm[1][w];
    }
}

// ---------------------------------------------------------------------------
// Kernel 2: transpose eps[d, m, l, u, dn] -> scratch[d, tri, m], only the
// realized (d,l,u) rows (OR of 64 group slices), only the realized dn band.
// block (32,8); grid (l=64, u=64, d=4).
// ---------------------------------------------------------------------------
__global__ void __launch_bounds__(256) eps_transpose(const float* __restrict__ eps) {
    const int l = blockIdx.x;
    const int u = blockIdx.y;
    const int d = blockIdx.z;
    if (u > l) return;

    const int tx = threadIdx.x;      // 0..31
    const int ty = threadIdx.y;      // 0..7
    const int t  = ty * 32 + tx;

    // OR-reduce the 64 group slices for this (d, l, u) word.
    __shared__ unsigned long long red[64];
    __shared__ unsigned long long s_mask;
    const int off = l * (l + 1) / 2 + u;
    if (t < 64) red[t] = g_slice[t][d][off];
    __syncthreads();
    if (t < 32) {
        unsigned long long v = red[t] | red[t + 32];
        #pragma unroll
        for (int o = 16; o > 0; o >>= 1)
            v |= __shfl_xor_sync(0xffffffffu, v, o);
        if (t == 0) s_mask = v;
    }
    __syncthreads();
    const unsigned long long mask = s_mask;
    if (mask == 0ull) return;

    const int dn0 = __ffsll((long long)mask) - 1;   // first realized dn
    const int dn1 = 63 - __clzll((long long)mask);  // last realized dn
    const int W   = dn1 - dn0;                      // band width - 1

    __shared__ float tile[64][65];   // [m][dn-dn0], padded: conflict-free

    const size_t in0 = (size_t)d * SD + (size_t)l * SL + (size_t)u * 65ull + dn0;
    #pragma unroll
    for (int m = ty; m < 64; m += 8) {
        const size_t r = in0 + (size_t)m * SM;
        if (tx <= W)      tile[m][tx]      = eps[r + tx];
        if (tx + 32 <= W) tile[m][tx + 32] = eps[r + tx + 32];
    }
    __syncthreads();

    const size_t ob = ((size_t)d * TRI + (size_t)loff(l) + (size_t)u * (l + 1)) * 64ull;
    for (int dn = dn0 + ty; dn <= dn1; dn += 8) {
        const size_t o = ob + (size_t)dn * 64ull;
        const int c = dn - dn0;
        g_scratch[o + tx]      = tile[tx][c];        // consecutive tx -> consecutive m
        g_scratch[o + tx + 32] = tile[tx + 32][c];
    }
}

// ---------------------------------------------------------------------------
// Kernel 3: per batch, ballot-prefix -> (u,dn) per site, product over 64
// coalesced scratch rows, reduce over m. block (64,4): x = m lane, ty = batch.
// ---------------------------------------------------------------------------
__global__ void __launch_bounds__(256) seggps_compute(const void* __restrict__ raw,
                                                      float* __restrict__ out) {
    __shared__ unsigned s_base[4][64];
    __shared__ unsigned s0[4][2], s1[4][2];
    __shared__ float    s_red[8];

    const int x  = threadIdx.x;   // 0..63 (site during scan, m lane during product)
    const int ty = threadIdx.y;   // 0..3
    const int b  = blockIdx.x * 4 + ty;

    const bool is64 = detect_is64(raw, x & 31);
    const int idx = load_idx(raw, (size_t)b * 64 + x, is64);

    const unsigned m0 = __ballot_sync(0xffffffffu, idx & 1);
    const unsigned m1 = __ballot_sync(0xffffffffu, idx & 2);
    const int half = x >> 5;
    if ((x & 31) == 0) { s0[ty][half] = m0; s1[ty][half] = m1; }
    __syncthreads();
    const unsigned lm = (1u << (x & 31)) - 1u;
    const int u  = __popc(m0 & lm) + (half ? __popc(s0[ty][0]) : 0);
    const int dn = __popc(m1 & lm) + (half ? __popc(s1[ty][0]) : 0);

    s_base[ty][x] = (unsigned)((idx * TRI + loff(x) + u * (x + 1) + dn) * 64);
    __syncthreads();

    // Product over sites: thread x = m lane; 64 coalesced 256B row reads.
    // 8 accumulators -> MLP 8 against L2 latency.
    float p0 = 1.f, p1 = 1.f, p2 = 1.f, p3 = 1.f;
    float p4 = 1.f, p5 = 1.f, p6 = 1.f, p7 = 1.f;
    #pragma unroll
    for (int l = 0; l < 64; l += 8) {
        p0 *= g_scratch[s_base[ty][l + 0] + x];
        p1 *= g_scratch[s_base[ty][l + 1] + x];
        p2 *= g_scratch[s_base[ty][l + 2] + x];
        p3 *= g_scratch[s_base[ty][l + 3] + x];
        p4 *= g_scratch[s_base[ty][l + 4] + x];
        p5 *= g_scratch[s_base[ty][l + 5] + x];
        p6 *= g_scratch[s_base[ty][l + 6] + x];
        p7 *= g_scratch[s_base[ty][l + 7] + x];
    }
    float prod = ((p0 * p1) * (p2 * p3)) * ((p4 * p5) * (p6 * p7));

    #pragma unroll
    for (int o = 16; o > 0; o >>= 1)
        prod += __shfl_xor_sync(0xffffffffu, prod, o);
    const int warp = (ty * 64 + x) >> 5;   // 0..7
    if ((x & 31) == 0) s_red[warp] = prod;
    __syncthreads();
    if (x == 0) out[b] = s_red[ty * 2] + s_red[ty * 2 + 1];
}

// ---------------------------------------------------------------------------
extern "C" void kernel_launch(void* const* d_in, const int* in_sizes, int n_in,
                              void* d_out, int out_size) {
    const float* eps = (const float*)d_in[1];
    float*       out = (float*)d_out;

    mark_tuples  <<<dim3(NGROUP, 2), dim3(64, 4)>>>(d_in[0]);
    eps_transpose<<<dim3(64, 64, 4), dim3(32, 8)>>>(eps);
    seggps_compute<<<8192 / 4, dim3(64, 4)>>>(d_in[0], out);
}

// round 8
// speedup vs baseline: 1.1480x; 1.1480x over previous
#include <cuda_runtime.h>

// Problem constants
static constexpr int LD  = 4;       // LOCAL_DIM
static constexpr int MD  = 64;      // M
static constexpr int TRI = 89440;   // sum_{k=1..64} k^2  (reachable (l,u,dn) tuples)

// epsilon strides (elements): shape (4, 64, 64, 65, 65) = (d, m, l, u, dn)
static constexpr unsigned long long SD = 17305600ull; // 64*64*65*65
static constexpr unsigned long long SM = 270400ull;   // 64*65*65
static constexpr unsigned long long SL = 4225ull;     // 65*65

static constexpr int NGROUP = 64;   // batch groups for the mark pass
static constexpr int NW     = 2080; // mask words per d: sum_l (l+1)

// Scratch: transposed reachable region, layout [d][loff(l)+u*(l+1)+dn][m]
__device__ float g_scratch[(size_t)LD * TRI * MD];
// Per-group realized-tuple mask slices (plain stores, OR-reduced by transpose)
__device__ unsigned long long g_slice[NGROUP][LD][NW];

__device__ __host__ __forceinline__ int loff(int l) {
    return l * (l + 1) * (2 * l + 1) / 6;   // sum_{k=1..l} k^2
}

// Per-warp dtype detection: words 1,3,..,63 of the indices buffer are all zero
// iff the buffer is int64 (values < 4). Always in-bounds under either dtype.
__device__ __forceinline__ bool detect_is64(const void* raw, int lane) {
    unsigned wodd = ((const unsigned*)raw)[2 * lane + 1];
    return __ballot_sync(0xffffffffu, wodd != 0u) == 0u;
}

__device__ __forceinline__ int load_idx(const void* raw, size_t pos, bool is64) {
    if (is64) return (int)((const long long*)raw)[pos];
    return ((const int*)raw)[pos];
}

// ---------------------------------------------------------------------------
// Kernel 1: mark realized (d,l,u,dn) tuples — latency-tolerant version.
// Grid (64 groups, 2 d-halves); block 256 = 8 warps. Warp w scans batches
// group*128 + w + 8p (p=0..15); lane owns sites (lane, lane+32). All prefix
// counts are intra-warp ballots -> NO block barrier in the hot loop, and all
// 32 index loads per lane are prefetched (MLP 32, one DRAM latency).
// ---------------------------------------------------------------------------
__global__ void __launch_bounds__(256) mark_tuples(const void* __restrict__ raw) {
    const int t     = threadIdx.x;         // 0..255
    const int w     = t >> 5;              // warp 0..7
    const int lane  = t & 31;
    const int group = blockIdx.x;          // 0..63
    const int dh    = blockIdx.y;          // 0..1: handles d = 2*dh, 2*dh+1

    __shared__ unsigned long long sm[2][NW];   // 33.3 KB
    for (int i = t; i < 2 * NW; i += 256)
        (&sm[0][0])[i] = 0ull;
    const bool is64 = detect_is64(raw, lane);
    __syncthreads();

    // Prefetch: 16 batches per warp, 2 sites per lane -> 32 independent loads.
    int i0[16], i1[16];
    #pragma unroll
    for (int p = 0; p < 16; ++p) {
        const size_t base = ((size_t)(group * 128 + w + 8 * p)) * 64;
        i0[p] = load_idx(raw, base + lane,      is64);
        i1[p] = load_idx(raw, base + lane + 32, is64);
    }

    const unsigned lm = (1u << lane) - 1u;
    const int so_lo = lane * (lane + 1) / 2;
    const int so_hi = (lane + 32) * (lane + 33) / 2;

    #pragma unroll
    for (int p = 0; p < 16; ++p) {
        const unsigned m0lo = __ballot_sync(0xffffffffu, i0[p] & 1);
        const unsigned m1lo = __ballot_sync(0xffffffffu, i0[p] & 2);
        const unsigned m0hi = __ballot_sync(0xffffffffu, i1[p] & 1);
        const unsigned m1hi = __ballot_sync(0xffffffffu, i1[p] & 2);

        const int u_lo  = __popc(m0lo & lm);
        const int dn_lo = __popc(m1lo & lm);
        const int u_hi  = __popc(m0lo) + __popc(m0hi & lm);
        const int dn_hi = __popc(m1lo) + __popc(m1hi & lm);

        if ((i0[p] >> 1) == dh)
            atomicOr(&sm[i0[p] & 1][so_lo + u_lo], 1ull << dn_lo);
        if ((i1[p] >> 1) == dh)
            atomicOr(&sm[i1[p] & 1][so_hi + u_hi], 1ull << dn_hi);
    }
    __syncthreads();

    for (int i = t; i < NW; i += 256) {
        g_slice[group][2 * dh + 0][i] = sm[0][i];
        g_slice[group][2 * dh + 1][i] = sm[1][i];
    }
}

// ---------------------------------------------------------------------------
// Kernel 2: transpose eps[d, m, l, u, dn] -> scratch[d, tri, m], only the
// realized (d,l,u) rows (OR of 64 group slices), only the realized dn band.
// block (32,8); grid (l=64, u=64, d=4).
// ---------------------------------------------------------------------------
__global__ void __launch_bounds__(256) eps_transpose(const float* __restrict__ eps) {
    const int l = blockIdx.x;
    const int u = blockIdx.y;
    const int d = blockIdx.z;
    if (u > l) return;

    const int tx = threadIdx.x;      // 0..31
    const int ty = threadIdx.y;      // 0..7
    const int t  = ty * 32 + tx;

    // OR-reduce the 64 group slices for this (d, l, u) word.
    __shared__ unsigned long long red[64];
    __shared__ unsigned long long s_mask;
    const int off = l * (l + 1) / 2 + u;
    if (t < 64) red[t] = g_slice[t][d][off];
    __syncthreads();
    if (t < 32) {
        unsigned long long v = red[t] | red[t + 32];
        #pragma unroll
        for (int o = 16; o > 0; o >>= 1)
            v |= __shfl_xor_sync(0xffffffffu, v, o);
        if (t == 0) s_mask = v;
    }
    __syncthreads();
    const unsigned long long mask = s_mask;
    if (mask == 0ull) return;

    const int dn0 = __ffsll((long long)mask) - 1;   // first realized dn
    const int dn1 = 63 - __clzll((long long)mask);  // last realized dn
    const int W   = dn1 - dn0;                      // band width - 1

    __shared__ float tile[64][65];   // [m][dn-dn0], padded: conflict-free

    const size_t in0 = (size_t)d * SD + (size_t)l * SL + (size_t)u * 65ull + dn0;
    #pragma unroll
    for (int m = ty; m < 64; m += 8) {
        const size_t r = in0 + (size_t)m * SM;
        if (tx <= W)      tile[m][tx]      = eps[r + tx];
        if (tx + 32 <= W) tile[m][tx + 32] = eps[r + tx + 32];
    }
    __syncthreads();

    const size_t ob = ((size_t)d * TRI + (size_t)loff(l) + (size_t)u * (l + 1)) * 64ull;
    for (int dn = dn0 + ty; dn <= dn1; dn += 8) {
        const size_t o = ob + (size_t)dn * 64ull;
        const int c = dn - dn0;
        g_scratch[o + tx]      = tile[tx][c];        // consecutive tx -> consecutive m
        g_scratch[o + tx + 32] = tile[tx + 32][c];
    }
}

// ---------------------------------------------------------------------------
// Kernel 3: per batch, ballot-prefix -> (u,dn) per site, product over 64
// coalesced scratch rows, reduce over m. block (64,4): x = m lane, ty = batch.
// ---------------------------------------------------------------------------
__global__ void __launch_bounds__(256) seggps_compute(const void* __restrict__ raw,
                                                      float* __restrict__ out) {
    __shared__ unsigned s_base[4][64];
    __shared__ unsigned s0[4][2], s1[4][2];
    __shared__ float    s_red[8];

    const int x  = threadIdx.x;   // 0..63 (site during scan, m lane during product)
    const int ty = threadIdx.y;   // 0..3
    const int b  = blockIdx.x * 4 + ty;

    const bool is64 = detect_is64(raw, x & 31);
    const int idx = load_idx(raw, (size_t)b * 64 + x, is64);

    const unsigned m0 = __ballot_sync(0xffffffffu, idx & 1);
    const unsigned m1 = __ballot_sync(0xffffffffu, idx & 2);
    const int half = x >> 5;
    if ((x & 31) == 0) { s0[ty][half] = m0; s1[ty][half] = m1; }
    __syncthreads();
    const unsigned lm = (1u << (x & 31)) - 1u;
    const int u  = __popc(m0 & lm) + (half ? __popc(s0[ty][0]) : 0);
    const int dn = __popc(m1 & lm) + (half ? __popc(s1[ty][0]) : 0);

    s_base[ty][x] = (unsigned)((idx * TRI + loff(x) + u * (x + 1) + dn) * 64);
    __syncthreads();

    // Product over sites: thread x = m lane; 64 coalesced 256B row reads.
    // 8 accumulators -> MLP 8 against L2 latency.
    float p0 = 1.f, p1 = 1.f, p2 = 1.f, p3 = 1.f;
    float p4 = 1.f, p5 = 1.f, p6 = 1.f, p7 = 1.f;
    #pragma unroll
    for (int l = 0; l < 64; l += 8) {
        p0 *= g_scratch[s_base[ty][l + 0] + x];
        p1 *= g_scratch[s_base[ty][l + 1] + x];
        p2 *= g_scratch[s_base[ty][l + 2] + x];
        p3 *= g_scratch[s_base[ty][l + 3] + x];
        p4 *= g_scratch[s_base[ty][l + 4] + x];
        p5 *= g_scratch[s_base[ty][l + 5] + x];
        p6 *= g_scratch[s_base[ty][l + 6] + x];
        p7 *= g_scratch[s_base[ty][l + 7] + x];
    }
    float prod = ((p0 * p1) * (p2 * p3)) * ((p4 * p5) * (p6 * p7));

    #pragma unroll
    for (int o = 16; o > 0; o >>= 1)
        prod += __shfl_xor_sync(0xffffffffu, prod, o);
    const int warp = (ty * 64 + x) >> 5;   // 0..7
    if ((x & 31) == 0) s_red[warp] = prod;
    __syncthreads();
    if (x == 0) out[b] = s_red[ty * 2] + s_red[ty * 2 + 1];
}

// ---------------------------------------------------------------------------
extern "C" void kernel_launch(void* const* d_in, const int* in_sizes, int n_in,
                              void* d_out, int out_size) {
    const float* eps = (const float*)d_in[1];
    float*       out = (float*)d_out;

    mark_tuples  <<<dim3(NGROUP, 2), 256>>>(d_in[0]);
    eps_transpose<<<dim3(64, 64, 4), dim3(32, 8)>>>(eps);
    seggps_compute<<<8192 / 4, dim3(64, 4)>>>(d_in[0], out);
}

// round 10
// speedup vs baseline: 1.1560x; 1.0069x over previous
#include <cuda_runtime.h>

// Problem constants
static constexpr int LD  = 4;       // LOCAL_DIM
static constexpr int MD  = 64;      // M
static constexpr int TRI = 89440;   // sum_{k=1..64} k^2  (reachable (l,u,dn) tuples)

// epsilon strides (elements): shape (4, 64, 64, 65, 65) = (d, m, l, u, dn)
static constexpr unsigned long long SD = 17305600ull; // 64*64*65*65
static constexpr unsigned long long SM = 270400ull;   // 64*65*65
static constexpr unsigned long long SL = 4225ull;     // 65*65

static constexpr int NGROUP = 256;  // batch groups for the range pass

// Scratch: transposed reachable region, layout [d][loff(l)+u*(l+1)+dn][m]
__device__ float g_scratch[(size_t)LD * TRI * MD];

// Realized ranges per (d,l): metric 0 = max u, 1 = max (63-u)  [umin = 63-v],
//                            metric 2 = max dn, 3 = max (63-dn) [dnmin = 63-v].
// Zero-initialized at module load; atomicMax converges to the same fixed point
// on every graph replay of identical inputs -> deterministic.
__device__ int g_rng[4][LD][64];

__device__ __host__ __forceinline__ int loff(int l) {
    return l * (l + 1) * (2 * l + 1) / 6;   // sum_{k=1..l} k^2
}

// Per-warp dtype detection: words 1,3,..,63 of the indices buffer are all zero
// iff the buffer is int64 (values < 4). Always in-bounds under either dtype.
__device__ __forceinline__ bool detect_is64(const void* raw, int lane) {
    unsigned wodd = ((const unsigned*)raw)[2 * lane + 1];
    return __ballot_sync(0xffffffffu, wodd != 0u) == 0u;
}

__device__ __forceinline__ int load_idx(const void* raw, size_t pos, bool is64) {
    if (is64) return (int)((const long long*)raw)[pos];
    return ((const int*)raw)[pos];
}

// ---------------------------------------------------------------------------
// Kernel 1: realized (u,dn) range per (d,l). Grid 256 blocks x 32 batches.
// Warp w handles 4 batches; lane owns sites (lane, lane+32). Intra-warp
// ballots only (no block barrier in the loop); smem atomicMax aggregation;
// 1024 spread global REDs per block at the end.
// ---------------------------------------------------------------------------
__global__ void __launch_bounds__(256) mark_ranges(const void* __restrict__ raw) {
    const int t     = threadIdx.x;         // 0..255
    const int w     = t >> 5;              // warp 0..7
    const int lane  = t & 31;
    const int group = blockIdx.x;          // 0..255

    __shared__ int s_rng[4][LD][64];       // 4 KB
    for (int i = t; i < 4 * LD * 64; i += 256)
        (&s_rng[0][0][0])[i] = 0;
    const bool is64 = detect_is64(raw, lane);
    __syncthreads();

    // Prefetch 4 batches per warp, 2 sites per lane -> 8 independent loads.
    int i0[4], i1[4];
    #pragma unroll
    for (int p = 0; p < 4; ++p) {
        const size_t base = ((size_t)(group * 32 + w * 4 + p)) * 64;
        i0[p] = load_idx(raw, base + lane,      is64);
        i1[p] = load_idx(raw, base + lane + 32, is64);
    }

    const unsigned lm = (1u << lane) - 1u;

    #pragma unroll
    for (int p = 0; p < 4; ++p) {
        const unsigned m0lo = __ballot_sync(0xffffffffu, i0[p] & 1);
        const unsigned m1lo = __ballot_sync(0xffffffffu, i0[p] & 2);
        const unsigned m0hi = __ballot_sync(0xffffffffu, i1[p] & 1);
        const unsigned m1hi = __ballot_sync(0xffffffffu, i1[p] & 2);

        const int u_lo  = __popc(m0lo & lm);
        const int dn_lo = __popc(m1lo & lm);
        const int u_hi  = __popc(m0lo) + __popc(m0hi & lm);
        const int dn_hi = __popc(m1lo) + __popc(m1hi & lm);

        atomicMax(&s_rng[0][i0[p]][lane],      u_lo);
        atomicMax(&s_rng[1][i0[p]][lane],      63 - u_lo);
        atomicMax(&s_rng[2][i0[p]][lane],      dn_lo);
        atomicMax(&s_rng[3][i0[p]][lane],      63 - dn_lo);
        atomicMax(&s_rng[0][i1[p]][lane + 32], u_hi);
        atomicMax(&s_rng[1][i1[p]][lane + 32], 63 - u_hi);
        atomicMax(&s_rng[2][i1[p]][lane + 32], dn_hi);
        atomicMax(&s_rng[3][i1[p]][lane + 32], 63 - dn_hi);
    }
    __syncthreads();

    #pragma unroll
    for (int k = 0; k < 4; ++k) {
        const int i = t + 256 * k;                 // 0..1023
        const int v = (&s_rng[0][0][0])[i];
        if (v > 0) atomicMax(&(&g_rng[0][0][0])[i], v);
    }
}

// ---------------------------------------------------------------------------
// Kernel 2: transpose eps[d, m, l, u, dn] -> scratch[d, tri, m], only the
// realized rectangle [umin..umax] x [dnmin..dnmax] per (d,l).
// block (32,8); grid (l=64, u=64, d=4).
// ---------------------------------------------------------------------------
__global__ void __launch_bounds__(256) eps_transpose(const float* __restrict__ eps) {
    const int l = blockIdx.x;
    const int u = blockIdx.y;
    const int d = blockIdx.z;

    const int umax  = g_rng[0][d][l];
    const int umin  = 63 - g_rng[1][d][l];
    if (u < umin || u > umax) return;
    const int dn1   = g_rng[2][d][l];          // dnmax (<= l by construction)
    const int dn0   = 63 - g_rng[3][d][l];     // dnmin
    if (dn0 > dn1) return;
    const int W = dn1 - dn0;                   // band width - 1

    const int tx = threadIdx.x;      // 0..31
    const int ty = threadIdx.y;      // 0..7

    __shared__ float tile[64][65];   // [m][dn-dn0], padded: conflict-free

    const size_t in0 = (size_t)d * SD + (size_t)l * SL + (size_t)u * 65ull + dn0;
    #pragma unroll
    for (int m = ty; m < 64; m += 8) {
        const size_t r = in0 + (size_t)m * SM;
        if (tx <= W)      tile[m][tx]      = eps[r + tx];
        if (tx + 32 <= W) tile[m][tx + 32] = eps[r + tx + 32];
    }
    __syncthreads();

    const size_t ob = ((size_t)d * TRI + (size_t)loff(l) + (size_t)u * (l + 1)) * 64ull;
    for (int dn = dn0 + ty; dn <= dn1; dn += 8) {
        const size_t o = ob + (size_t)dn * 64ull;
        const int c = dn - dn0;
        g_scratch[o + tx]      = tile[tx][c];        // consecutive tx -> consecutive m
        g_scratch[o + tx + 32] = tile[tx + 32][c];
    }
}

// ---------------------------------------------------------------------------
// Kernel 3: per batch, ballot-prefix -> (u,dn) per site, product over 64
// coalesced scratch rows, reduce over m. block (64,4): x = m lane, ty = batch.
// ---------------------------------------------------------------------------
__global__ void __launch_bounds__(256) seggps_compute(const void* __restrict__ raw,
                                                      float* __restrict__ out) {
    __shared__ unsigned s_base[4][64];
    __shared__ unsigned s0[4][2], s1[4][2];
    __shared__ float    s_red[8];

    const int x  = threadIdx.x;   // 0..63 (site during scan, m lane during product)
    const int ty = threadIdx.y;   // 0..3
    const int b  = blockIdx.x * 4 + ty;

    const bool is64 = detect_is64(raw, x & 31);
    const int idx = load_idx(raw, (size_t)b * 64 + x, is64);

    const unsigned m0 = __ballot_sync(0xffffffffu, idx & 1);
    const unsigned m1 = __ballot_sync(0xffffffffu, idx & 2);
    const int half = x >> 5;
    if ((x & 31) == 0) { s0[ty][half] = m0; s1[ty][half] = m1; }
    __syncthreads();
    const unsigned lm = (1u << (x & 31)) - 1u;
    const int u  = __popc(m0 & lm) + (half ? __popc(s0[ty][0]) : 0);
    const int dn = __popc(m1 & lm) + (half ? __popc(s1[ty][0]) : 0);

    s_base[ty][x] = (unsigned)((idx * TRI + loff(x) + u * (x + 1) + dn) * 64);
    __syncthreads();

    // Product over sites: thread x = m lane; 64 coalesced 256B row reads.
    // 8 accumulators -> MLP 8 against L2 latency.
    float p0 = 1.f, p1 = 1.f, p2 = 1.f, p3 = 1.f;
    float p4 = 1.f, p5 = 1.f, p6 = 1.f, p7 = 1.f;
    #pragma unroll
    for (int l = 0; l < 64; l += 8) {
        p0 *= g_scratch[s_base[ty][l + 0] + x];
        p1 *= g_scratch[s_base[ty][l + 1] + x];
        p2 *= g_scratch[s_base[ty][l + 2] + x];
        p3 *= g_scratch[s_base[ty][l + 3] + x];
        p4 *= g_scratch[s_base[ty][l + 4] + x];
        p5 *= g_scratch[s_base[ty][l + 5] + x];
        p6 *= g_scratch[s_base[ty][l + 6] + x];
        p7 *= g_scratch[s_base[ty][l + 7] + x];
    }
    float prod = ((p0 * p1) * (p2 * p3)) * ((p4 * p5) * (p6 * p7));

    #pragma unroll
    for (int o = 16; o > 0; o >>= 1)
        prod += __shfl_xor_sync(0xffffffffu, prod, o);
    const int warp = (ty * 64 + x) >> 5;   // 0..7
    if ((x & 31) == 0) s_red[warp] = prod;
    __syncthreads();
    if (x == 0) out[b] = s_red[ty * 2] + s_red[ty * 2 + 1];
}

// ---------------------------------------------------------------------------
extern "C" void kernel_launch(void* const* d_in, const int* in_sizes, int n_in,
                              void* d_out, int out_size) {
    const float* eps = (const float*)d_in[1];
    float*       out = (float*)d_out;

    mark_ranges  <<<NGROUP, 256>>>(d_in[0]);
    eps_transpose<<<dim3(64, 64, 4), dim3(32, 8)>>>(eps);
    seggps_compute<<<8192 / 4, dim3(64, 4)>>>(d_in[0], out);
}

// round 11
// speedup vs baseline: 1.2141x; 1.0503x over previous
#include <cuda_runtime.h>
#include <cuda_fp16.h>

// Problem constants
static constexpr int LD  = 4;       // LOCAL_DIM
static constexpr int MD  = 64;      // M
static constexpr int TRI = 89440;   // sum_{k=1..64} k^2  (reachable (l,u,dn) tuples)

// epsilon strides (elements): shape (4, 64, 64, 65, 65) = (d, m, l, u, dn)
static constexpr unsigned long long SD = 17305600ull; // 64*64*65*65
static constexpr unsigned long long SM = 270400ull;   // 64*65*65
static constexpr unsigned long long SL = 4225ull;     // 65*65

// Scratch: fp16 LOG of the realized region, layout [d][loff(l)+u*(l+1)+dn][m/2]
// (half2 packs m-pair (2k, 2k+1)). 4*89440*32 half2 = 45.8 MB.
__device__ __half2 g_scratch2[(size_t)LD * TRI * (MD / 2)];

// Realized ranges per (d,l): metric 0 = max u, 1 = max (63-u)  [umin = 63-v],
//                            metric 2 = max dn, 3 = max (63-dn) [dnmin = 63-v].
// Zero-init at load; atomicMax converges to the same fixed point each replay.
__device__ int g_rng[4][LD][64];

__device__ __host__ __forceinline__ int loff(int l) {
    return l * (l + 1) * (2 * l + 1) / 6;   // sum_{k=1..l} k^2
}

// Per-warp dtype detection: words 1,3,..,63 of the indices buffer are all zero
// iff the buffer is int64 (values < 4). Always in-bounds under either dtype.
__device__ __forceinline__ bool detect_is64(const void* raw, int lane) {
    unsigned wodd = ((const unsigned*)raw)[2 * lane + 1];
    return __ballot_sync(0xffffffffu, wodd != 0u) == 0u;
}

__device__ __forceinline__ int load_idx(const void* raw, size_t pos, bool is64) {
    if (is64) return (int)((const long long*)raw)[pos];
    return ((const int*)raw)[pos];
}

// ---------------------------------------------------------------------------
// Kernel 1: realized (u,dn) range per (d,l). Grid 512 x block 256; warp w
// handles 2 batches; lane owns sites (lane, lane+32). Intra-warp ballots only;
// smem atomicMax aggregation; spread global REDs at the end.
// ---------------------------------------------------------------------------
__global__ void __launch_bounds__(256) mark_ranges(const void* __restrict__ raw) {
    const int t     = threadIdx.x;         // 0..255
    const int w     = t >> 5;              // warp 0..7
    const int lane  = t & 31;
    const int group = blockIdx.x;          // 0..511

    __shared__ int s_rng[4][LD][64];       // 4 KB
    for (int i = t; i < 4 * LD * 64; i += 256)
        (&s_rng[0][0][0])[i] = 0;
    const bool is64 = detect_is64(raw, lane);
    __syncthreads();

    // Prefetch 2 batches per warp, 2 sites per lane -> 4 independent loads.
    int i0[2], i1[2];
    #pragma unroll
    for (int p = 0; p < 2; ++p) {
        const size_t base = ((size_t)(group * 16 + w * 2 + p)) * 64;
        i0[p] = load_idx(raw, base + lane,      is64);
        i1[p] = load_idx(raw, base + lane + 32, is64);
    }

    const unsigned lm = (1u << lane) - 1u;

    #pragma unroll
    for (int p = 0; p < 2; ++p) {
        const unsigned m0lo = __ballot_sync(0xffffffffu, i0[p] & 1);
        const unsigned m1lo = __ballot_sync(0xffffffffu, i0[p] & 2);
        const unsigned m0hi = __ballot_sync(0xffffffffu, i1[p] & 1);
        const unsigned m1hi = __ballot_sync(0xffffffffu, i1[p] & 2);

        const int u_lo  = __popc(m0lo & lm);
        const int dn_lo = __popc(m1lo & lm);
        const int u_hi  = __popc(m0lo) + __popc(m0hi & lm);
        const int dn_hi = __popc(m1lo) + __popc(m1hi & lm);

        atomicMax(&s_rng[0][i0[p]][lane],      u_lo);
        atomicMax(&s_rng[1][i0[p]][lane],      63 - u_lo);
        atomicMax(&s_rng[2][i0[p]][lane],      dn_lo);
        atomicMax(&s_rng[3][i0[p]][lane],      63 - dn_lo);
        atomicMax(&s_rng[0][i1[p]][lane + 32], u_hi);
        atomicMax(&s_rng[1][i1[p]][lane + 32], 63 - u_hi);
        atomicMax(&s_rng[2][i1[p]][lane + 32], dn_hi);
        atomicMax(&s_rng[3][i1[p]][lane + 32], 63 - dn_hi);
    }
    __syncthreads();

    #pragma unroll
    for (int k = 0; k < 4; ++k) {
        const int i = t + 256 * k;                 // 0..1023
        const int v = (&s_rng[0][0][0])[i];
        if (v > 0) atomicMax(&(&g_rng[0][0][0])[i], v);
    }
}

// ---------------------------------------------------------------------------
// Kernel 2: transpose eps[d, m, l, u, dn] -> log-fp16 scratch[d, tri, m],
// only the realized rectangle [umin..umax] x [dnmin..dnmax] per (d,l).
// block (32,8); grid (l=64, u=64, d=4).
// ---------------------------------------------------------------------------
__global__ void __launch_bounds__(256) eps_transpose(const float* __restrict__ eps) {
    const int l = blockIdx.x;
    const int u = blockIdx.y;
    const int d = blockIdx.z;

    const int umax  = g_rng[0][d][l];
    const int umin  = 63 - g_rng[1][d][l];
    if (u < umin || u > umax) return;
    const int dn1   = g_rng[2][d][l];          // dnmax
    const int dn0   = 63 - g_rng[3][d][l];     // dnmin
    if (dn0 > dn1) return;
    const int W = dn1 - dn0;                   // band width - 1

    const int tx = threadIdx.x;      // 0..31
    const int ty = threadIdx.y;      // 0..7

    __shared__ float tile[64][65];   // [m][dn-dn0], log values, padded

    const size_t in0 = (size_t)d * SD + (size_t)l * SL + (size_t)u * 65ull + dn0;
    #pragma unroll
    for (int m = ty; m < 64; m += 8) {
        const size_t r = in0 + (size_t)m * SM;
        if (tx <= W)      tile[m][tx]      = __logf(eps[r + tx]);
        if (tx + 32 <= W) tile[m][tx + 32] = __logf(eps[r + tx + 32]);
    }
    __syncthreads();

    // Row of 32 half2 (m-pairs) per realized (dn); fully coalesced 128B stores.
    const size_t ob2 = ((size_t)d * TRI + (size_t)loff(l) + (size_t)u * (l + 1)) * 32ull;
    for (int dn = dn0 + ty; dn <= dn1; dn += 8) {
        const int c = dn - dn0;
        g_scratch2[ob2 + (size_t)dn * 32ull + tx] =
            __floats2half2_rn(tile[2 * tx][c], tile[2 * tx + 1][c]);
    }
}

// ---------------------------------------------------------------------------
// Kernel 3: warp-per-batch. Lane owns sites (lane, lane+32) for the scan and
// m-pair (2*lane, 2*lane+1) for the accumulation. No block barriers at all.
// Sum fp32 logs over 64 sites (8x float2 accumulators), exp, reduce over m.
// Grid 1024 x block 256 (8 batches per block).
// ---------------------------------------------------------------------------
__global__ void __launch_bounds__(256) seggps_compute(const void* __restrict__ raw,
                                                      float* __restrict__ out) {
    __shared__ unsigned s_base[8][64];

    const int t    = threadIdx.x;
    const int w    = t >> 5;
    const int lane = t & 31;
    const int b    = blockIdx.x * 8 + w;

    const bool is64 = detect_is64(raw, lane);
    const size_t base = (size_t)b * 64;
    const int i0 = load_idx(raw, base + lane,      is64);
    const int i1 = load_idx(raw, base + lane + 32, is64);

    const unsigned m0lo = __ballot_sync(0xffffffffu, i0 & 1);
    const unsigned m1lo = __ballot_sync(0xffffffffu, i0 & 2);
    const unsigned m0hi = __ballot_sync(0xffffffffu, i1 & 1);
    const unsigned m1hi = __ballot_sync(0xffffffffu, i1 & 2);

    const unsigned lm = (1u << lane) - 1u;
    const int u_lo  = __popc(m0lo & lm);
    const int dn_lo = __popc(m1lo & lm);
    const int u_hi  = __popc(m0lo) + __popc(m0hi & lm);
    const int dn_hi = __popc(m1lo) + __popc(m1hi & lm);

    const int s_hi = lane + 32;
    s_base[w][lane] = (unsigned)((i0 * TRI + loff(lane) + u_lo * (lane + 1) + dn_lo) * 32);
    s_base[w][s_hi] = (unsigned)((i1 * TRI + loff(s_hi) + u_hi * (s_hi + 1) + dn_hi) * 32);
    __syncwarp();

    // Sum of logs over 64 sites; 8 float2 accumulators = 16 FADD chains, MLP 8.
    float2 a0 = {0.f, 0.f}, a1 = {0.f, 0.f}, a2 = {0.f, 0.f}, a3 = {0.f, 0.f};
    float2 a4 = {0.f, 0.f}, a5 = {0.f, 0.f}, a6 = {0.f, 0.f}, a7 = {0.f, 0.f};
    #pragma unroll
    for (int l = 0; l < 64; l += 8) {
        const float2 v0 = __half22float2(g_scratch2[s_base[w][l + 0] + lane]);
        const float2 v1 = __half22float2(g_scratch2[s_base[w][l + 1] + lane]);
        const float2 v2 = __half22float2(g_scratch2[s_base[w][l + 2] + lane]);
        const float2 v3 = __half22float2(g_scratch2[s_base[w][l + 3] + lane]);
        const float2 v4 = __half22float2(g_scratch2[s_base[w][l + 4] + lane]);
        const float2 v5 = __half22float2(g_scratch2[s_base[w][l + 5] + lane]);
        const float2 v6 = __half22float2(g_scratch2[s_base[w][l + 6] + lane]);
        const float2 v7 = __half22float2(g_scratch2[s_base[w][l + 7] + lane]);
        a0.x += v0.x; a0.y += v0.y;  a1.x += v1.x; a1.y += v1.y;
        a2.x += v2.x; a2.y += v2.y;  a3.x += v3.x; a3.y += v3.y;
        a4.x += v4.x; a4.y += v4.y;  a5.x += v5.x; a5.y += v5.y;
        a6.x += v6.x; a6.y += v6.y;  a7.x += v7.x; a7.y += v7.y;
    }
    const float sx = ((a0.x + a1.x) + (a2.x + a3.x)) + ((a4.x + a5.x) + (a6.x + a7.x));
    const float sy = ((a0.y + a1.y) + (a2.y + a3.y)) + ((a4.y + a5.y) + (a6.y + a7.y));

    // Two m-products per lane; sum the 64 products across the warp.
    float p = __expf(sx) + __expf(sy);
    #pragma unroll
    for (int o = 16; o > 0; o >>= 1)
        p += __shfl_xor_sync(0xffffffffu, p, o);
    if (lane == 0) out[b] = p;
}

// ---------------------------------------------------------------------------
extern "C" void kernel_launch(void* const* d_in, const int* in_sizes, int n_in,
                              void* d_out, int out_size) {
    const float* eps = (const float*)d_in[1];
    float*       out = (float*)d_out;

    mark_ranges  <<<512, 256>>>(d_in[0]);
    eps_transpose<<<dim3(64, 64, 4), dim3(32, 8)>>>(eps);
    seggps_compute<<<8192 / 8, 256>>>(d_in[0], out);
}